// round 9
// baseline (speedup 1.0000x reference)
#include <cuda_runtime.h>
#include <cstddef>
#include <cstdint>

// Problem constants (fixed by the reference setup)
#define BATCH 32
#define SEQ   512
#define DIM   1024
#define NCOLS (BATCH * DIM)   // 32768 independent columns
#define CHUNK 16              // scan steps per pipeline stage
#define STAGES 3              // smem ring depth (3 x 16 x 1KB = 48 KB)
#define NCHUNK (SEQ / CHUNK)  // 32

// 1.0f / 0.001f correctly rounded = 999.99994f. For sp in {0,1},
// sp / 0.001f == sp * 999.99994f bitwise (1*c and 0*c are exact).
#define SPIKE_OUT 999.99994f

// floor(a) for a in [0,2) as a float-valued compare: FSET emits 1.0f/0.0f in
// a float register — fixed-lat 4, no predicate.
__device__ __forceinline__ float ge1(float a)
{
    float one;
    asm("set.ge.f32.f32 %0, %1, %2;" : "=f"(one) : "f"(a), "f"(1.0f));
    return one;
}

// One scan step = 4 substeps of {v += r; sp = floor(v); v -= sp;}, bitwise-
// faithful. With v in [0,1) and 0 <= r < 1:  a = v + r lies in [0, 2), so
// floor(a) == ge1(a) in {0.0f, 1.0f} and v' = a - ge1(a) is the literal
// reference subtraction. Pure chain: FADD(4)->FSET(4)->FADD(4) per substep.
// Only the LAST substep's spike survives. Returns spike / DT.
__device__ __forceinline__ float step4(float& v, float r)
{
    #pragma unroll
    for (int i = 0; i < 3; ++i) {
        const float a = v + r;
        v = a - ge1(a);
    }
    const float a   = v + r;
    const float one = ge1(a);
    v = a - one;
    return one * SPIKE_OUT;      // off the chain
}

__global__ __launch_bounds__(256, 1)
void dual_threshold_scan_kernel(const float* __restrict__ inputs,
                                const float* __restrict__ init_state,
                                float* __restrict__ out)
{
    // Ring of input tiles: stage -> CHUNK rows x 256 cols (this block's slice).
    __shared__ float stage_buf[STAGES][CHUNK][256];   // 49152 B

    const int tid = threadIdx.x;
    const int col = blockIdx.x * 256 + tid;      // grid 128 x 256 == NCOLS

    // Block-uniform coordinates: 4 blocks per batch row.
    const int b_blk = blockIdx.x >> 2;           // batch index
    const int d0    = (blockIdx.x & 3) * 256;    // first dim col of this block

    // Fetch role: 4 x 16B cp.async per thread per chunk.
    const int frow  = tid >> 6;                  // 0..3
    const int fcol4 = (tid & 63) * 4;            // 16B-aligned float offset
    const float* fsrc = inputs + (size_t)b_blk * SEQ * DIM + d0 + fcol4;

    // Issue one chunk's loads as one commit group.
    auto issue_chunk = [&](int c) {
        const int st = c % STAGES;
        #pragma unroll
        for (int r = 0; r < 4; ++r) {
            const float* g = fsrc + (size_t)(c * CHUNK + frow + 4 * r) * DIM;
            uint32_t s = (uint32_t)__cvta_generic_to_shared(
                &stage_buf[st][frow + 4 * r][fcol4]);
            asm volatile("cp.async.cg.shared.global [%0], [%1], 16;"
                         :: "r"(s), "l"(g));
        }
        asm volatile("cp.async.commit_group;" ::: "memory");
    };

    // Prologue: groups for chunks 0..STAGES-2 in flight (32-step lookahead).
    #pragma unroll
    for (int c = 0; c < STAGES - 1; ++c)
        issue_chunk(c);

    const size_t base = (size_t)b_blk * SEQ * DIM + d0 + tid;
    float* __restrict__ op = out + base;

    float v = init_state[col];

    for (int k = 0; k < NCHUNK; ++k) {
        // Issued so far: chunks 0..k+STAGES-2. Allowing STAGES-2 pending
        // groups forces chunk k's group complete (FIFO).
        asm volatile("cp.async.wait_group %0;" :: "n"(STAGES - 2) : "memory");
        __syncthreads();   // publish smem writes across threads

        const int st = k % STAGES;

        // Phase 1: pull all 16 rates into registers. The 16 LDS issue
        // back-to-back so their ~29-cyc latencies overlap; FMNMX/FMUL are
        // off the v-chain entirely.
        float rr[CHUNK];
        #pragma unroll
        for (int j = 0; j < CHUNK; ++j)
            rr[j] = fmaxf(stage_buf[st][j][tid], 0.0f) * 0.001f;  // relu * DT

        // Phase 2: pure serial chain — 12 x 4-cyc ops per step, operands
        // register-resident. Stores are off-chain.
        #pragma unroll
        for (int j = 0; j < CHUNK; ++j)
            __stcs(op + (size_t)(k * CHUNK + j) * DIM, step4(v, rr[j]));

        // Refill: chunk k+STAGES-1 overwrites the stage read in iter k-1
        // (the barrier above ordered those reads first). Empty commit groups
        // in the tail keep the wait_group arithmetic exact.
        const int kn = k + STAGES - 1;
        if (kn < NCHUNK) issue_chunk(kn);
        else asm volatile("cp.async.commit_group;" ::: "memory");
    }
}

extern "C" void kernel_launch(void* const* d_in, const int* in_sizes, int n_in,
                              void* d_out, int out_size)
{
    const float* inputs     = (const float*)d_in[0];  // [32, 512, 1024] f32
    const float* init_state = (const float*)d_in[1];  // [32, 1024] f32
    float*       out        = (float*)d_out;          // [32, 512, 1024] f32

    (void)in_sizes; (void)n_in; (void)out_size;

    dual_threshold_scan_kernel<<<128, 256>>>(inputs, init_state, out);
}

// round 11
// speedup vs baseline: 1.0614x; 1.0614x over previous
#include <cuda_runtime.h>
#include <cstddef>
#include <cstdint>

// Problem constants (fixed by the reference setup)
#define BATCH 32
#define SEQ   512
#define DIM   1024
#define NCOLS (BATCH * DIM)   // 32768 independent columns
#define CHUNK 16              // scan steps per pipeline stage
#define STAGES 3              // per-warp smem ring depth
#define NCHUNK (SEQ / CHUNK)  // 32
#define WARPS  8              // 256 threads / 32

// 1.0f / 0.001f correctly rounded = 999.99994f. For sp in {0,1},
// sp / 0.001f == sp * 999.99994f bitwise (1*c and 0*c are exact).
#define SPIKE_OUT 999.99994f

// floor(a) for a in [0,2) as a float-valued compare: FSET emits 1.0f/0.0f in
// a float register — fixed-lat, no predicate.
__device__ __forceinline__ float ge1(float a)
{
    float one;
    asm("set.ge.f32.f32 %0, %1, %2;" : "=f"(one) : "f"(a), "f"(1.0f));
    return one;
}

// One scan step = 4 substeps of {v += r; sp = floor(v); v -= sp;}, bitwise-
// faithful. With v in [0,1) and 0 <= r < 1:  a = v + r lies in [0, 2), so
// floor(a) == ge1(a) in {0.0f, 1.0f} and v' = a - ge1(a) is the literal
// reference subtraction. Only the LAST substep's spike survives.
__device__ __forceinline__ float step4(float& v, float r)
{
    #pragma unroll
    for (int i = 0; i < 3; ++i) {
        const float a = v + r;
        v = a - ge1(a);
    }
    const float a   = v + r;
    const float one = ge1(a);
    v = a - one;
    return one * SPIKE_OUT;      // off the chain
}

__global__ __launch_bounds__(256, 1)
void dual_threshold_scan_kernel(const float* __restrict__ inputs,
                                const float* __restrict__ init_state,
                                float* __restrict__ out)
{
    // Per-warp private ring: warp -> stage -> CHUNK rows x 32 cols. 48 KB.
    __shared__ float stage_buf[WARPS][STAGES][CHUNK][32];

    const int tid  = threadIdx.x;
    const int wid  = tid >> 5;
    const int lane = tid & 31;
    const int col  = blockIdx.x * 256 + tid;     // grid 128 x 256 == NCOLS

    const int b_blk = blockIdx.x >> 2;           // batch index
    const int d0    = (blockIdx.x & 3) * 256;    // first dim col of this block

    // Warp w owns columns [d0 + w*32, +32). Fetch role within the warp:
    // round r (0..3): lane L copies 16B of row (L>>3)+4r at float col (L&7)*4.
    const int frow  = lane >> 3;                 // 0..3
    const int fcol4 = (lane & 7) * 4;            // 16B-aligned float offset
    const float* fsrc = inputs + (size_t)b_blk * SEQ * DIM + d0 + wid * 32 + fcol4;

    float (&ring)[STAGES][CHUNK][32] = stage_buf[wid];

    // Issue one chunk's loads as one commit group (warp-local; each thread's
    // group tracks its own 4 copies).
    auto issue_chunk = [&](int c) {
        const int st = c % STAGES;
        #pragma unroll
        for (int r = 0; r < 4; ++r) {
            const float* g = fsrc + (size_t)(c * CHUNK + frow + 4 * r) * DIM;
            uint32_t s = (uint32_t)__cvta_generic_to_shared(
                &ring[st][frow + 4 * r][fcol4]);
            asm volatile("cp.async.cg.shared.global [%0], [%1], 16;"
                         :: "r"(s), "l"(g));
        }
        asm volatile("cp.async.commit_group;" ::: "memory");
    };

    // Prologue: 32-step lookahead in flight.
    #pragma unroll
    for (int c = 0; c < STAGES - 1; ++c)
        issue_chunk(c);

    const size_t base = (size_t)b_blk * SEQ * DIM + d0 + tid;
    float* __restrict__ op = out + base;

    float v = init_state[col];

    for (int k = 0; k < NCHUNK; ++k) {
        // Every lane waits for its own copies of chunk k (FIFO: allow
        // STAGES-2 pending), then __syncwarp publishes all lanes' smem
        // writes warp-wide. No cross-warp coupling.
        asm volatile("cp.async.wait_group %0;" :: "n"(STAGES - 2) : "memory");
        __syncwarp();

        const int st = k % STAGES;

        // Rates into registers (off the v-chain).
        float rr[CHUNK];
        #pragma unroll
        for (int j = 0; j < CHUNK; ++j)
            rr[j] = fmaxf(ring[st][j][lane], 0.0f) * 0.001f;  // relu * DT

        // Pure serial chain; stores off-chain.
        #pragma unroll
        for (int j = 0; j < CHUNK; ++j)
            __stcs(op + (size_t)(k * CHUNK + j) * DIM, step4(v, rr[j]));

        // WAR on the ring is warp-local: the __syncwarp above ordered this
        // warp's reads of stage (k-1)%STAGES before this refill.
        __syncwarp();
        const int kn = k + STAGES - 1;
        if (kn < NCHUNK) issue_chunk(kn);
        else asm volatile("cp.async.commit_group;" ::: "memory");
    }
}

extern "C" void kernel_launch(void* const* d_in, const int* in_sizes, int n_in,
                              void* d_out, int out_size)
{
    const float* inputs     = (const float*)d_in[0];  // [32, 512, 1024] f32
    const float* init_state = (const float*)d_in[1];  // [32, 1024] f32
    float*       out        = (float*)d_out;          // [32, 512, 1024] f32

    (void)in_sizes; (void)n_in; (void)out_size;

    dual_threshold_scan_kernel<<<128, 256>>>(inputs, init_state, out);
}

// round 12
// speedup vs baseline: 1.0643x; 1.0028x over previous
#include <cuda_runtime.h>
#include <cstddef>
#include <cstdint>

// Problem constants (fixed by the reference setup)
#define BATCH 32
#define SEQ   512
#define DIM   1024
#define NCOLS (BATCH * DIM)   // 32768 independent columns
#define CHUNK 16              // scan steps per pipeline stage
#define STAGES 3              // per-warp smem ring depth
#define NCHUNK (SEQ / CHUNK)  // 32
#define WARPS  4              // 128 threads / 32
#define CPW    64             // columns per warp (2 per thread)

// 1.0f / 0.001f correctly rounded = 999.99994f. For sp in {0,1},
// sp / 0.001f == sp * 999.99994f bitwise (1*c and 0*c are exact).
#define SPIKE_OUT 999.99994f

// Float-valued compare: compiles to FSETP + SEL (pred-as-data, 4-cyc), the
// fastest exact form on sm_10x (no FSET; @P-guard path would be 13 cyc).
__device__ __forceinline__ float ge1(float a)
{
    float one;
    asm("set.ge.f32.f32 %0, %1, %2;" : "=f"(one) : "f"(a), "f"(1.0f));
    return one;
}

// One scan step = 4 substeps of {v += r; sp = floor(v); v -= sp;}, bitwise-
// faithful. With v in [0,1) and 0 <= r < 1:  a = v + r lies in [0, 2), so
// floor(a) == ge1(a) in {0.0f, 1.0f} and v' = a - ge1(a) is the literal
// reference subtraction. Only the LAST substep's spike survives.
__device__ __forceinline__ float step4(float& v, float r)
{
    #pragma unroll
    for (int i = 0; i < 3; ++i) {
        const float a = v + r;
        v = a - ge1(a);
    }
    const float a   = v + r;
    const float one = ge1(a);
    v = a - one;
    return one * SPIKE_OUT;      // off the chain
}

__global__ __launch_bounds__(128, 1)
void dual_threshold_scan_kernel(const float* __restrict__ inputs,
                                const float* __restrict__ init_state,
                                float* __restrict__ out)
{
    // Per-warp private ring: warp -> stage -> CHUNK rows x 64 cols. 48 KB.
    __shared__ float stage_buf[WARPS][STAGES][CHUNK][CPW];

    const int tid  = threadIdx.x;
    const int wid  = tid >> 5;
    const int lane = tid & 31;

    const int b_blk = blockIdx.x >> 2;           // batch index
    const int d0    = (blockIdx.x & 3) * 256;    // first dim col of this block

    // Warp w owns columns [d0 + w*64, +64); thread handles cols 2*lane, 2*lane+1.
    // Fetch role: 8 x 16B cp.async per thread per chunk. Round r (0..7):
    // lane L copies 16B of row 2r+(L>>4) at float col (L&15)*4 of the 64-wide tile.
    const int frow = lane >> 4;                  // 0..1
    const int fseg = (lane & 15) * 4;            // 16B-aligned float offset
    const float* fsrc = inputs + (size_t)b_blk * SEQ * DIM + d0 + wid * CPW + fseg;

    float (&ring)[STAGES][CHUNK][CPW] = stage_buf[wid];

    auto issue_chunk = [&](int c) {
        const int st = c % STAGES;
        #pragma unroll
        for (int r = 0; r < 8; ++r) {
            const float* g = fsrc + (size_t)(c * CHUNK + 2 * r + frow) * DIM;
            uint32_t s = (uint32_t)__cvta_generic_to_shared(
                &ring[st][2 * r + frow][fseg]);
            asm volatile("cp.async.cg.shared.global [%0], [%1], 16;"
                         :: "r"(s), "l"(g));
        }
        asm volatile("cp.async.commit_group;" ::: "memory");
    };

    // Prologue: 32-step lookahead in flight.
    #pragma unroll
    for (int c = 0; c < STAGES - 1; ++c)
        issue_chunk(c);

    const int col0 = b_blk * DIM + d0 + wid * CPW + 2 * lane;   // global column
    float* __restrict__ op =
        out + (size_t)b_blk * SEQ * DIM + d0 + wid * CPW + 2 * lane;

    float2 vv = *reinterpret_cast<const float2*>(init_state + col0);
    float v0 = vv.x, v1 = vv.y;

    for (int k = 0; k < NCHUNK; ++k) {
        // FIFO: allow STAGES-2 pending groups -> chunk k's group complete,
        // then __syncwarp publishes all lanes' smem writes warp-wide.
        asm volatile("cp.async.wait_group %0;" :: "n"(STAGES - 2) : "memory");
        __syncwarp();

        const int st = k % STAGES;

        // Rates into registers (off the v-chain), LDS.64 per step.
        float2 rr[CHUNK];
        #pragma unroll
        for (int j = 0; j < CHUNK; ++j) {
            const float2 x = *reinterpret_cast<const float2*>(
                &ring[st][j][2 * lane]);
            rr[j].x = fmaxf(x.x, 0.0f) * 0.001f;   // relu * DT
            rr[j].y = fmaxf(x.y, 0.0f) * 0.001f;
        }

        // Two independent serial chains per thread, interleaved by ptxas:
        // doubles per-SMSP chain throughput at unchanged latency.
        #pragma unroll
        for (int j = 0; j < CHUNK; ++j) {
            float2 o;
            o.x = step4(v0, rr[j].x);
            o.y = step4(v1, rr[j].y);
            __stcs(reinterpret_cast<float2*>(op + (size_t)(k * CHUNK + j) * DIM), o);
        }

        // WAR on the ring is warp-local: the __syncwarp above ordered this
        // warp's reads of stage (k-1)%STAGES before this refill.
        __syncwarp();
        const int kn = k + STAGES - 1;
        if (kn < NCHUNK) issue_chunk(kn);
        else asm volatile("cp.async.commit_group;" ::: "memory");
    }
}

extern "C" void kernel_launch(void* const* d_in, const int* in_sizes, int n_in,
                              void* d_out, int out_size)
{
    const float* inputs     = (const float*)d_in[0];  // [32, 512, 1024] f32
    const float* init_state = (const float*)d_in[1];  // [32, 1024] f32
    float*       out        = (float*)d_out;          // [32, 512, 1024] f32

    (void)in_sizes; (void)n_in; (void)out_size;

    // 128 blocks x 128 threads x 2 cols/thread = 32768 columns, one wave.
    dual_threshold_scan_kernel<<<128, 128>>>(inputs, init_state, out);
}